// round 17
// baseline (speedup 1.0000x reference)
#include <cuda_runtime.h>
#include <cuda_bf16.h>

#define BB 512
#define SS 512
#define CC 96
#define NB 8
#define ALL_T 96
#define SUP 144                 // ushort stride per s_u row (288B)
#define EW 384                  // E words (bf16x2) per timestep

__device__ float g_num[BB];
__device__ float g_den[BB];
__device__ unsigned g_E[(size_t)(BB / NB) * SS * EW];   // precomputed exp(em), bf16x2

__device__ __forceinline__ float fast_rcp(float x) {
    float r;
    asm("rcp.approx.f32 %0, %1;" : "=f"(r) : "f"(x));
    return r;
}
__device__ __forceinline__ unsigned pack_bf16(float x, float y) {
    __nv_bfloat162 h = __floats2bfloat162_rn(x, y);
    return *reinterpret_cast<unsigned*>(&h);
}
__device__ __forceinline__ unsigned pk2f(float lo, float hi) {   // d.lo = lo
    unsigned d;
    asm("cvt.rn.bf16x2.f32 %0, %1, %2;" : "=r"(d) : "f"(hi), "f"(lo));
    return d;
}
__device__ __forceinline__ unsigned hmul2(unsigned a, unsigned b) {
    unsigned d;
    asm("mul.bf16x2 %0, %1, %2;" : "=r"(d) : "r"(a), "r"(b));
    return d;
}
__device__ __forceinline__ float lo_bf16(unsigned w) {
    unsigned short h = (unsigned short)(w & 0xffff);
    __nv_bfloat16 b = *reinterpret_cast<__nv_bfloat16*>(&h);
    return __bfloat162float(b);
}
__device__ __forceinline__ void mma_bf16(
    float& d0, float& d1, float& d2, float& d3,
    unsigned a0, unsigned a1, unsigned a2, unsigned a3,
    unsigned b0, unsigned b1)
{
    asm volatile(
        "mma.sync.aligned.m16n8k16.row.col.f32.bf16.bf16.f32 "
        "{%0,%1,%2,%3},{%4,%5,%6,%7},{%8,%9},{%0,%1,%2,%3};"
        : "+f"(d0), "+f"(d1), "+f"(d2), "+f"(d3)
        : "r"(a0), "r"(a1), "r"(a2), "r"(a3), "r"(b0), "r"(b1));
}
__device__ __forceinline__ void cp_async16(void* dst, const void* src) {
    unsigned d = (unsigned)__cvta_generic_to_shared(dst);
    asm volatile("cp.async.cg.shared.global [%0], [%1], 16;" :: "r"(d), "l"(src));
}
#define CP_COMMIT() asm volatile("cp.async.commit_group;" ::: "memory")
#define CP_WAIT4()  asm volatile("cp.async.wait_group 4;" ::: "memory")
#define CP_WAIT0()  asm volatile("cp.async.wait_group 0;" ::: "memory")

// =====================================================================
// Pass 1: E[t] = exp(em) in bf16x2, laid out per (bb, t) block as
// word[p*8+nb] = (E[state 16g+j], E[state 16g+j+8]), p = 8g+j.
// =====================================================================
__global__ __launch_bounds__(256) void crf_exp_kernel(const float* __restrict__ em)
{
    const int bx = blockIdx.x;              // (bb, t)
    const int bb = bx >> 9, t = bx & (SS - 1);
    __shared__ unsigned short st[NB][CC];
    const int tid = threadIdx.x;
    for (int k = tid; k < NB * CC; k += 256) {
        int nb = k / CC, s = k - nb * CC;
        float v = __expf(em[((size_t)(bb * NB + nb) * SS + t) * CC + s]);
        __nv_bfloat16 h = __float2bfloat16(v);
        st[nb][s] = *reinterpret_cast<unsigned short*>(&h);
    }
    __syncthreads();
    unsigned* dst = g_E + (size_t)bx * EW;
    for (int k = tid; k < EW; k += 256) {
        int p = k >> 3, nb = k & 7;
        int g = p >> 3, j = p & 7;
        int s0 = 16 * g + j;
        dst[k] = (unsigned)st[nb][s0] | ((unsigned)st[nb][s0 + 8] << 16);
    }
}

// =====================================================================
// Pass 2: fused forward (warp 0, barrier-free) + numerator (warps 1-2).
// 64 CTAs x 96 threads. Forward warp: 36 MMAs/step, A resident in 144
// regs with sigma-relabeled k; u as 12 bf16x2 regs; __syncwarp only.
// =====================================================================
__global__ __launch_bounds__(ALL_T, 1) void crf_fused_kernel(
    const float* __restrict__ em,
    const int* __restrict__ tags,
    const int* __restrict__ masks,
    const float* __restrict__ start,
    const float* __restrict__ endt,
    const float* __restrict__ trans)
{
    __shared__ unsigned short s_u[2][NB][SUP];
    __shared__ unsigned s_E[8][EW];
    __shared__ int s_mk[NB][SS];
    __shared__ unsigned s_r[4][NB];
    __shared__ float s_ee[CC];
    __shared__ float s_S[NB];

    const int tid = threadIdx.x;
    const int b0g = blockIdx.x * NB;

    // ================= numerator warps (1-2) =================
    if (tid >= 32) {
        const int w2 = (tid >> 5) - 1;      // 0..1
        const int lane = tid & 31;
#pragma unroll
        for (int k = 0; k < 4; k++) {
            const int b = b0g + w2 * 4 + k;
            const int* tg = tags + (size_t)b * SS;
            const int* mk = masks + (size_t)b * SS;
            const float* e = em + (size_t)b * SS * CC;
            float s = 0.f;
            int cnt = 0;
            for (int t = lane; t < SS; t += 32) {
                int tagt = tg[t];
                int m = mk[t];
                cnt += m ? 1 : 0;
                if (t == 0) {
                    s += start[tagt] + e[tagt];
                } else if (m) {
                    int tp = tg[t - 1];
                    s += trans[tp * CC + tagt] + e[(size_t)t * CC + tagt];
                }
            }
#pragma unroll
            for (int o = 16; o; o >>= 1) {
                s += __shfl_xor_sync(0xFFFFFFFFu, s, o);
                cnt += __shfl_xor_sync(0xFFFFFFFFu, cnt, o);
            }
            if (lane == 0) g_num[b] = s + endt[tg[cnt - 1]];
        }
        return;
    }

    // ================= forward warp =================
    const int lane = tid;
    const int lr = lane >> 2;           // B/D row group
    const int lc = lane & 3;
    const int n0 = 2 * lc, n1 = n0 + 1; // batches

    // A fragments, sigma-relabeled k: slot pair (2lc,2lc+1) carries
    // states (k0, k0+8); slot pair (2lc+8,2lc+9) carries (k0+1, k0+9).
    unsigned A[36][4];
#pragma unroll
    for (int mt = 0; mt < 6; mt++) {
        int s0 = 16 * mt + lr, s1 = s0 + 8;
#pragma unroll
        for (int kt = 0; kt < 6; kt++) {
            int k0 = 16 * kt + 2 * lc;
            A[mt * 6 + kt][0] = pack_bf16(__expf(trans[(k0 + 0) * CC + s0]), __expf(trans[(k0 + 8) * CC + s0]));
            A[mt * 6 + kt][1] = pack_bf16(__expf(trans[(k0 + 0) * CC + s1]), __expf(trans[(k0 + 8) * CC + s1]));
            A[mt * 6 + kt][2] = pack_bf16(__expf(trans[(k0 + 1) * CC + s0]), __expf(trans[(k0 + 9) * CC + s0]));
            A[mt * 6 + kt][3] = pack_bf16(__expf(trans[(k0 + 1) * CC + s1]), __expf(trans[(k0 + 9) * CC + s1]));
        }
    }

    // t = 0: u as 12 bf16x2 regs, stored in permuted layout (16mt+2lr, +1)
    unsigned u2[6][2];
    float S0 = 0.f, S1 = 0.f;
#pragma unroll
    for (int mt = 0; mt < 6; mt++) {
        int s0 = 16 * mt + lr, s1 = s0 + 8;
        float a00 = __expf(start[s0] + em[(size_t)(b0g + n0) * SS * CC + s0]);
        float a10 = __expf(start[s1] + em[(size_t)(b0g + n0) * SS * CC + s1]);
        float a01 = __expf(start[s0] + em[(size_t)(b0g + n1) * SS * CC + s0]);
        float a11 = __expf(start[s1] + em[(size_t)(b0g + n1) * SS * CC + s1]);
        u2[mt][0] = pk2f(a00, a10);
        u2[mt][1] = pk2f(a01, a11);
        *(unsigned*)&s_u[0][n0][16 * mt + 2 * lr] = u2[mt][0];
        *(unsigned*)&s_u[0][n1][16 * mt + 2 * lr] = u2[mt][1];
    }
    if (lr == 0) {   // lanes 0-3: normalizers for all 8 batches
        __nv_bfloat16 ra = __float2bfloat16(fast_rcp(lo_bf16(u2[0][0])));
        __nv_bfloat16 rb = __float2bfloat16(fast_rcp(lo_bf16(u2[0][1])));
        unsigned rwa = *reinterpret_cast<unsigned short*>(&ra);
        unsigned rwb = *reinterpret_cast<unsigned short*>(&rb);
        rwa |= rwa << 16; rwb |= rwb << 16;
        s_r[1][n0] = rwa; s_r[2][n0] = rwa;
        s_r[1][n1] = rwb; s_r[2][n1] = rwb;
    }
    for (int j = lane; j < CC; j += 32) {
        int ps = 16 * (j >> 4) + 2 * (j & 7) + ((j & 15) >> 3);
        s_ee[ps] = __expf(endt[j]);
    }

    // prologue: masks (whole sequence) + E slots 1..7
#pragma unroll
    for (int nb = 0; nb < NB; nb++) {
#pragma unroll
        for (int c = 0; c < 4; c++)
            cp_async16(&s_mk[nb][lane * 16 + c * 4],
                       masks + (size_t)(b0g + nb) * SS + lane * 16 + c * 4);
    }
    CP_COMMIT();
    const unsigned* Eg = g_E + (size_t)blockIdx.x * SS * EW;
#pragma unroll
    for (int tt = 1; tt <= 7; tt++) {
#pragma unroll
        for (int c = 0; c < 3; c++)
            cp_async16((char*)s_E[tt] + lane * 16 + c * 512,
                       (const char*)(Eg + (size_t)tt * EW) + lane * 16 + c * 512);
        CP_COMMIT();
    }
    CP_WAIT4();              // masks + E slots 1..3 complete
    __syncwarp();

    int p = 0;
    for (int t = 1; t < SS; t++) {
        // prefetch E slot t+7
        int tp = t + 7;
        if (tp < SS) {
#pragma unroll
            for (int c = 0; c < 3; c++)
                cp_async16((char*)s_E[tp & 7] + lane * 16 + c * 512,
                           (const char*)(Eg + (size_t)tp * EW) + lane * 16 + c * 512);
        }
        CP_COMMIT();

        int m0 = s_mk[n0][t], m1 = s_mk[n1][t];
        unsigned r0w = s_r[t & 3][n0], r1w = s_r[t & 3][n1];

        // B fragments: 6 LDS.64 from permuted u
        uint2 bb[6];
#pragma unroll
        for (int kt = 0; kt < 6; kt++)
            bb[kt] = *(const uint2*)&s_u[p][lr][16 * kt + 4 * lc];

        // 36 MMAs: 6 interleaved chains (one per mt), depth 6
        float d[6][4];
#pragma unroll
        for (int mt = 0; mt < 6; mt++)
            d[mt][0] = d[mt][1] = d[mt][2] = d[mt][3] = 0.f;
#pragma unroll
        for (int kt = 0; kt < 6; kt++)
#pragma unroll
            for (int mt = 0; mt < 6; mt++)
                mma_bf16(d[mt][0], d[mt][1], d[mt][2], d[mt][3],
                         A[mt * 6 + kt][0], A[mt * 6 + kt][1],
                         A[mt * 6 + kt][2], A[mt * 6 + kt][3],
                         bb[kt].x, bb[kt].y);

        const int pn = p ^ 1;
        const int eslot = t & 7;
#pragma unroll
        for (int mt = 0; mt < 6; mt++) {
            uint2 ev = *(const uint2*)&s_E[eslot][(8 * mt + lr) * 8 + 2 * lc];
            unsigned v0 = hmul2(hmul2(pk2f(d[mt][0], d[mt][2]), ev.x), r0w);
            unsigned v1 = hmul2(hmul2(pk2f(d[mt][1], d[mt][3]), ev.y), r1w);
            u2[mt][0] = m0 ? v0 : u2[mt][0];
            u2[mt][1] = m1 ? v1 : u2[mt][1];
            *(unsigned*)&s_u[pn][n0][16 * mt + 2 * lr] = u2[mt][0];
            *(unsigned*)&s_u[pn][n1][16 * mt + 2 * lr] = u2[mt][1];
        }
        if (lr == 0) {
            // shift update for applied r; publish normalizer for t+2
            float lg0 = __logf(lo_bf16(r0w));
            float lg1 = __logf(lo_bf16(r1w));
            S0 = m0 ? S0 - lg0 : S0;
            S1 = m1 ? S1 - lg1 : S1;
            __nv_bfloat16 ra = __float2bfloat16(fast_rcp(lo_bf16(u2[0][0])));
            __nv_bfloat16 rb = __float2bfloat16(fast_rcp(lo_bf16(u2[0][1])));
            unsigned rwa = *reinterpret_cast<unsigned short*>(&ra);
            unsigned rwb = *reinterpret_cast<unsigned short*>(&rb);
            s_r[(t + 2) & 3][n0] = rwa | (rwa << 16);
            s_r[(t + 2) & 3][n1] = rwb | (rwb << 16);
        }

        CP_WAIT4();
        __syncwarp();
        p ^= 1;
    }

    if (lr == 0) { s_S[n0] = S0; s_S[n1] = S1; }
    __syncwarp();
    if (lane < NB) {
        const unsigned short* ur = s_u[p][lane];
        float s = 0.f;
        for (int j = 0; j < CC; j++) {
            unsigned short h = ur[j];
            __nv_bfloat16 b = *reinterpret_cast<__nv_bfloat16*>(&h);
            s += __bfloat162float(b) * s_ee[j];
        }
        g_den[b0g + lane] = s_S[lane] + __logf(s);
    }
}

// =====================================================================
// Final mean reduce
// =====================================================================
__global__ void crf_reduce_kernel(float* __restrict__ out)
{
    __shared__ float sh[BB];
    int t = threadIdx.x;
    sh[t] = g_num[t] - g_den[t];
    __syncthreads();
#pragma unroll
    for (int o = BB / 2; o > 0; o >>= 1) {
        if (t < o) sh[t] += sh[t + o];
        __syncthreads();
    }
    if (t == 0) out[0] = sh[0] * (1.0f / (float)BB);
}

extern "C" void kernel_launch(void* const* d_in, const int* in_sizes, int n_in,
                              void* d_out, int out_size)
{
    const float* em    = (const float*)d_in[0];
    const int*   tags  = (const int*)d_in[1];
    const int*   masks = (const int*)d_in[2];
    const float* start = (const float*)d_in[3];
    const float* endt  = (const float*)d_in[4];
    const float* trans = (const float*)d_in[5];
    float* out = (float*)d_out;

    crf_exp_kernel<<<(BB / NB) * SS, 256>>>(em);
    crf_fused_kernel<<<BB / NB, ALL_T>>>(em, tags, masks, start, endt, trans);
    crf_reduce_kernel<<<1, BB>>>(out);
}